// round 4
// baseline (speedup 1.0000x reference)
#include <cuda_runtime.h>
#include <math.h>

#define NN     20000
#define NEDGE  320000

typedef unsigned long long u64;

// ---------------- device scratch ----------------
__device__ float4 g_xsv[NN * 64];                 // (xv0,xv1,xv2,xs) per node-channel
__device__ float  g_tpw[(size_t)NEDGE * 320];     // edge MLP output, CSR-ordered
__device__ float  g_msg_s[NN * 128];
__device__ float  g_msg_v[NN * 768];              // [node][ch(192)][4] padded
__device__ int    g_cnt[NN];
__device__ int    g_off[NN + 1];
__device__ int    g_fill[NN];
__device__ int    g_pos[NEDGE];                   // edge -> CSR slot
__device__ int    g_ni_r[NEDGE];                  // CSR-ordered iedges
__device__ float4 g_ea_r[NEDGE];                  // CSR-ordered edge_attrs

// ---------------- constants ----------------
#define INV_SQRT_C    0.125f
#define INV_SQRT_NB   0.3535533905932738f
#define INV_SQRT_64   0.125f
#define INV_SQRT_2C   0.08838834764831845f
#define INV_SQRT_3C   0.07216878364870323f
#define INV_SQRT3     0.5773502691896258f
#define INV_SQRT2     0.7071067811865476f

// ---------------- f32x2 helpers ----------------
__device__ __forceinline__ u64 ffma2(u64 a, u64 b, u64 c) {
    u64 d;
    asm("fma.rn.f32x2 %0, %1, %2, %3;" : "=l"(d) : "l"(a), "l"(b), "l"(c));
    return d;
}
__device__ __forceinline__ u64 dup2(float x) {
    u64 d; unsigned r = __float_as_uint(x);
    asm("mov.b64 %0, {%1, %1};" : "=l"(d) : "r"(r));
    return d;
}
__device__ __forceinline__ float2 unpk(u64 v) {
    unsigned lo, hi;
    asm("mov.b64 {%0, %1}, %2;" : "=r"(lo), "=r"(hi) : "l"(v));
    return make_float2(__uint_as_float(lo), __uint_as_float(hi));
}

// ================= CSR =================
__global__ void kc_zero() {
    int i = blockIdx.x * 256 + threadIdx.x;
    if (i < NN) g_cnt[i] = 0;
}
__global__ void __launch_bounds__(1024) kc_scan() {
    __shared__ int part[1024];
    int tid = threadIdx.x;
    int base = tid * 20;
    int loc[20];
    int s = 0;
    #pragma unroll
    for (int i = 0; i < 20; i++) {
        int g = base + i;
        int v = (g < NN) ? g_cnt[g] : 0;
        loc[i] = s; s += v;
    }
    part[tid] = s;
    __syncthreads();
    for (int off = 1; off < 1024; off <<= 1) {
        int v = (tid >= off) ? part[tid - off] : 0;
        __syncthreads();
        part[tid] += v;
        __syncthreads();
    }
    int pre = (tid == 0) ? 0 : part[tid - 1];
    #pragma unroll
    for (int i = 0; i < 20; i++) {
        int g = base + i;
        if (g < NN) { int o = pre + loc[i]; g_off[g] = o; g_fill[g] = o; }
    }
    if (tid == 0) g_off[NN] = NEDGE;
}
__global__ void kc_fill(const int* __restrict__ jedges,
                        const int* __restrict__ iedges,
                        const float* __restrict__ edge_attrs) {
    int e = blockIdx.x * 256 + threadIdx.x;
    if (e < NEDGE) {
        int pos = atomicAdd(&g_fill[jedges[e]], 1);
        g_pos[e]   = pos;
        g_ni_r[pos] = iedges[e];
        g_ea_r[pos] = ((const float4*)edge_attrs)[e];
    }
}

// ================= Kernel 1: node up-projection (+ fused jedges histogram) ==
__global__ void __launch_bounds__(256) k_node_up(
    const float* __restrict__ node_feats,
    const float* __restrict__ Wup0,
    const float* __restrict__ Wup1,
    const int*   __restrict__ jedges)
{
    __shared__ float w0s[4096];
    __shared__ float w1s[4096];
    __shared__ float fs[4 * 256];
    int tid = threadIdx.x;
    for (int i = tid; i < 4096; i += 256) { w0s[i] = Wup0[i]; w1s[i] = Wup1[i]; }

    // fused histogram for CSR
    int gtid = blockIdx.x * 256 + tid;
    int gstr = gridDim.x * 256;
    for (int e = gtid; e < NEDGE; e += gstr) atomicAdd(&g_cnt[jedges[e]], 1);

    int ln = tid >> 6;
    int k  = tid & 63;
    for (int base = blockIdx.x * 4; base < NN; base += gridDim.x * 4) {
        __syncthreads();
        for (int i = tid; i < 1024; i += 256) fs[i] = node_feats[base * 256 + i];
        __syncthreads();
        const float* f = fs + ln * 256;
        float accs = 0.f, av0 = 0.f, av1 = 0.f, av2 = 0.f;
        #pragma unroll 8
        for (int c = 0; c < 64; c++) {
            float w0 = w0s[c * 64 + k];
            float w1 = w1s[c * 64 + k];
            accs += f[c] * w0;
            av0  += f[64 + 3 * c + 0] * w1;
            av1  += f[64 + 3 * c + 1] * w1;
            av2  += f[64 + 3 * c + 2] * w1;
        }
        int node = base + ln;
        g_xsv[node * 64 + k] = make_float4(av0 * INV_SQRT_C, av1 * INV_SQRT_C,
                                           av2 * INV_SQRT_C, accs * INV_SQRT_C);
    }
}

// ================= Kernel 2: edge MLP (f32x2, packed weights) ===============
// Weights pre-packed in SMEM: for each row-pair jp and column-pair l,
// ulonglong2 { (W[2jp][2l],W[2jp][2l+1]), (W[2jp+1][2l],W[2jp+1][2l+1]) }.
// Activations bounce through per-warp SMEM dup-packed; LDS.128 per edge per
// j-pair. Layer 4 split into two 4-edge halves to cap register pressure.
__global__ void __launch_bounds__(384, 1) k2_mlp(
    const float* __restrict__ edge_feats,
    const float* __restrict__ Wm1,
    const float* __restrict__ Wm2,
    const float* __restrict__ Wm3,
    const float* __restrict__ Wm4,
    float c_silu)
{
    extern __shared__ float sm[];
    float* w1p = sm;                 // 512
    float* w2p = sm + 512;           // 4096
    float* w3p = sm + 4608;          // 4096
    float* w4p = sm + 8704;          // 20480
    u64* hb = (u64*)(sm + 29184);    // 12 warps * 1024 u64

    int tid = threadIdx.x;
    // pack Wm1 (8x64)
    for (int i = tid; i < 512; i += 384) {
        int jp = i >> 7, r = i & 127, l = r >> 2, q = r & 3;
        w1p[i] = Wm1[(2 * jp + (q >> 1)) * 64 + 2 * l + (q & 1)] * INV_SQRT_NB;
    }
    // pack Wm2, Wm3 (64x64)
    for (int i = tid; i < 4096; i += 384) {
        int jp = i >> 7, r = i & 127, l = r >> 2, q = r & 3;
        int src = (2 * jp + (q >> 1)) * 64 + 2 * l + (q & 1);
        w2p[i] = Wm2[src] * INV_SQRT_64;
        w3p[i] = Wm3[src] * INV_SQRT_64;
    }
    // pack Wm4 (64x320) as [b][jp][l]
    for (int i = tid; i < 20480; i += 384) {
        int b = i >> 12, r = i & 4095, jp = r >> 7, rr = r & 127, l = rr >> 2, q = rr & 3;
        w4p[i] = Wm4[(2 * jp + (q >> 1)) * 320 + b * 64 + 2 * l + (q & 1)] * INV_SQRT_64;
    }
    __syncthreads();

    const ulonglong2* w1v = (const ulonglong2*)w1p;
    const ulonglong2* w2v = (const ulonglong2*)w2p;
    const ulonglong2* w3v = (const ulonglong2*)w3p;
    const ulonglong2* w4v = (const ulonglong2*)w4p;

    int warp = tid >> 5, lane = tid & 31;
    int k2l = lane * 2;
    u64* bufA = hb + warp * 1024;
    u64* bufB = bufA + 512;

    for (int e0 = (blockIdx.x * 12 + warp) * 8; e0 < NEDGE; e0 += gridDim.x * 12 * 8) {
        // load edge feats dup-packed into bufA[e][i], i<8
        #pragma unroll
        for (int r = 0; r < 2; r++) {
            int idx = lane + r * 32;
            int el = idx >> 3, i = idx & 7;
            bufA[el * 64 + i] = dup2(edge_feats[(e0 + el) * 8 + i]);
        }
        __syncwarp();

        u64 acc[8];
        // ---- layer 1: 8 -> 64 ----
        #pragma unroll
        for (int e = 0; e < 8; e++) acc[e] = 0ull;
        #pragma unroll
        for (int jp = 0; jp < 4; jp++) {
            ulonglong2 w = w1v[jp * 32 + lane];
            #pragma unroll
            for (int e = 0; e < 8; e++) {
                ulonglong2 h = *(const ulonglong2*)(bufA + e * 64 + 2 * jp);
                acc[e] = ffma2(h.x, w.x, acc[e]);
                acc[e] = ffma2(h.y, w.y, acc[e]);
            }
        }
        #pragma unroll
        for (int e = 0; e < 8; e++) {
            float2 f = unpk(acc[e]);
            f.x = c_silu * f.x / (1.f + __expf(-f.x));
            f.y = c_silu * f.y / (1.f + __expf(-f.y));
            *(ulonglong2*)(bufB + e * 64 + k2l) = make_ulonglong2(dup2(f.x), dup2(f.y));
        }
        __syncwarp();

        // ---- layer 2: 64 -> 64 ----
        #pragma unroll
        for (int e = 0; e < 8; e++) acc[e] = 0ull;
        #pragma unroll 4
        for (int jp = 0; jp < 32; jp++) {
            ulonglong2 w = w2v[jp * 32 + lane];
            #pragma unroll
            for (int e = 0; e < 8; e++) {
                ulonglong2 h = *(const ulonglong2*)(bufB + e * 64 + 2 * jp);
                acc[e] = ffma2(h.x, w.x, acc[e]);
                acc[e] = ffma2(h.y, w.y, acc[e]);
            }
        }
        #pragma unroll
        for (int e = 0; e < 8; e++) {
            float2 f = unpk(acc[e]);
            f.x = c_silu * f.x / (1.f + __expf(-f.x));
            f.y = c_silu * f.y / (1.f + __expf(-f.y));
            *(ulonglong2*)(bufA + e * 64 + k2l) = make_ulonglong2(dup2(f.x), dup2(f.y));
        }
        __syncwarp();

        // ---- layer 3: 64 -> 64 ----
        #pragma unroll
        for (int e = 0; e < 8; e++) acc[e] = 0ull;
        #pragma unroll 4
        for (int jp = 0; jp < 32; jp++) {
            ulonglong2 w = w3v[jp * 32 + lane];
            #pragma unroll
            for (int e = 0; e < 8; e++) {
                ulonglong2 h = *(const ulonglong2*)(bufA + e * 64 + 2 * jp);
                acc[e] = ffma2(h.x, w.x, acc[e]);
                acc[e] = ffma2(h.y, w.y, acc[e]);
            }
        }
        #pragma unroll
        for (int e = 0; e < 8; e++) {
            float2 f = unpk(acc[e]);
            f.x = c_silu * f.x / (1.f + __expf(-f.x));
            f.y = c_silu * f.y / (1.f + __expf(-f.y));
            *(ulonglong2*)(bufB + e * 64 + k2l) = make_ulonglong2(dup2(f.x), dup2(f.y));
        }
        __syncwarp();

        // ---- layer 4: 64 -> 320, two 4-edge halves (register pressure) ----
        #pragma unroll
        for (int half = 0; half < 2; half++) {
            u64 tp[4][5];
            #pragma unroll
            for (int e = 0; e < 4; e++)
                #pragma unroll
                for (int b = 0; b < 5; b++) tp[e][b] = 0ull;

            #pragma unroll 2
            for (int jp = 0; jp < 32; jp++) {
                ulonglong2 wv[5];
                #pragma unroll
                for (int b = 0; b < 5; b++) wv[b] = w4v[(b * 32 + jp) * 32 + lane];
                #pragma unroll
                for (int e = 0; e < 4; e++) {
                    ulonglong2 h = *(const ulonglong2*)(bufB + (half * 4 + e) * 64 + 2 * jp);
                    #pragma unroll
                    for (int b = 0; b < 5; b++) {
                        tp[e][b] = ffma2(h.x, wv[b].x, tp[e][b]);
                        tp[e][b] = ffma2(h.y, wv[b].y, tp[e][b]);
                    }
                }
            }
            #pragma unroll
            for (int e = 0; e < 4; e++) {
                int pos = g_pos[e0 + half * 4 + e];
                float* dst = g_tpw + (size_t)pos * 320 + k2l;
                #pragma unroll
                for (int b = 0; b < 5; b++) *(u64*)(dst + b * 64) = tp[e][b];
            }
        }
        __syncwarp();
    }
}

// ================= Kernel 3a: CSR gather — messages, no atomics =============
__global__ void __launch_bounds__(256) k3a_gather()
{
    int tid = threadIdx.x;
    int nl = tid >> 6;
    int c  = tid & 63;
    int node = blockIdx.x * 4 + nl;
    if (node >= NN) return;
    int beg = g_off[node], end = g_off[node + 1];

    float ms0 = 0.f, ms1 = 0.f;
    float m20 = 0.f, m21 = 0.f, m22 = 0.f;
    float m30 = 0.f, m31 = 0.f, m32 = 0.f;
    float m40 = 0.f, m41 = 0.f, m42 = 0.f;

    #pragma unroll 2
    for (int p = beg; p < end; p++) {
        int ni = g_ni_r[p];
        float4 ea = g_ea_r[p];                        // (eas, ev0, ev1, ev2)
        const float* tw = g_tpw + (size_t)p * 320;    // sequential stream
        float wa = tw[c], wb = tw[64 + c], wc = tw[128 + c], wd = tw[192 + c], we = tw[256 + c];
        float4 x = g_xsv[(size_t)ni * 64 + c];        // (xv0, xv1, xv2, xs)

        ms0 += wa * x.w * ea.x;
        ms1 += wb * (x.x * ea.y + x.y * ea.z + x.z * ea.w) * INV_SQRT3;
        float t2 = wc * x.w;
        m20 += t2 * ea.y; m21 += t2 * ea.z; m22 += t2 * ea.w;
        float t3 = wd * ea.x;
        m30 += t3 * x.x;  m31 += t3 * x.y;  m32 += t3 * x.z;
        float wei = we * INV_SQRT2;
        m40 += wei * (x.y * ea.w - x.z * ea.z);
        m41 += wei * (x.z * ea.y - x.x * ea.w);
        m42 += wei * (x.x * ea.z - x.y * ea.y);
    }

    g_msg_s[node * 128 + c]      = ms0;
    g_msg_s[node * 128 + 64 + c] = ms1;
    float4* mv = (float4*)(g_msg_v + (size_t)node * 768);
    mv[c]       = make_float4(m20, m21, m22, 0.f);
    mv[64 + c]  = make_float4(m30, m31, m32, 0.f);
    mv[128 + c] = make_float4(m40, m41, m42, 0.f);
}

// ================= Kernel 3b: node linear + polynomial mixing + output ======
__global__ void __launch_bounds__(256) k3b_node_out(
    const float* __restrict__ Wl0, const float* __restrict__ Wl1,
    const int*   __restrict__ atomic_numbers,
    const float* __restrict__ Ws0c1, const float* __restrict__ Ws0c2, const float* __restrict__ Ws0c3,
    const float* __restrict__ Ws1c1, const float* __restrict__ Ws1c2, const float* __restrict__ Ws1c3,
    const float* __restrict__ Wp0,   const float* __restrict__ Wp1,
    float* __restrict__ out)
{
    extern __shared__ float sm[];
    float* wl0s = sm;              // 8192
    float* wl1s = wl0s + 8192;     // 12288
    float* wp0s = wl1s + 12288;    // 4096
    float* wp1s = wp0s + 4096;     // 4096
    float* msgs = wp1s + 4096;     // 512
    float* msgv = msgs + 512;      // 3072 (4 nodes * 768)
    float* outs = msgv + 3072;     // 256
    float* outv = outs + 256;      // 768   total 33280 floats

    int tid = threadIdx.x;
    for (int i = tid; i < 8192;  i += 256) wl0s[i] = Wl0[i];
    for (int i = tid; i < 12288; i += 256) wl1s[i] = Wl1[i];
    for (int i = tid; i < 4096;  i += 256) { wp0s[i] = Wp0[i]; wp1s[i] = Wp1[i]; }

    int ln = tid >> 6;
    int k  = tid & 63;
    for (int base = blockIdx.x * 4; base < NN; base += gridDim.x * 4) {
        __syncthreads();
        for (int i = tid; i < 512;  i += 256) msgs[i] = g_msg_s[(size_t)base * 128 + i];
        for (int i = tid; i < 3072; i += 256) msgv[i] = g_msg_v[(size_t)base * 768 + i];
        __syncthreads();

        int node = base + ln;
        const float* ms = msgs + ln * 128;
        const float* mv = msgv + ln * 768;

        float s2 = 0.f;
        #pragma unroll 8
        for (int c = 0; c < 128; c++) s2 += ms[c] * wl0s[c * 64 + k];
        s2 *= INV_SQRT_2C;

        float v20 = 0.f, v21 = 0.f, v22 = 0.f;
        #pragma unroll 4
        for (int c = 0; c < 192; c++) {
            float w = wl1s[c * 64 + k];
            v20 += mv[c * 4 + 0] * w;
            v21 += mv[c * 4 + 1] * w;
            v22 += mv[c * 4 + 2] * w;
        }
        v20 *= INV_SQRT_3C; v21 *= INV_SQRT_3C; v22 *= INV_SQRT_3C;

        float vv = v20 * v20 + v21 * v21 + v22 * v22;
        int z = atomic_numbers[node];
        float w01  = Ws0c1[z * 64 + k];
        float w02a = Ws0c2[z * 128 + k];
        float w02b = Ws0c2[z * 128 + 64 + k];
        float w03a = Ws0c3[z * 128 + k];
        float w03b = Ws0c3[z * 128 + 64 + k];
        float w11  = Ws1c1[z * 64 + k];
        float w12  = Ws1c2[z * 64 + k];
        float w13a = Ws1c3[z * 128 + k];
        float w13b = Ws1c3[z * 128 + 64 + k];

        float vvs = vv * INV_SQRT3;
        float s2s = s2 * s2;
        float os   = w01 * s2 + w02a * s2s + w02b * vvs + w03a * s2s * s2 + w03b * s2 * vvs;
        float coef = w11 + w12 * s2 + w13a * s2s + w13b * vvs;

        outs[ln * 64 + k] = os;
        float* ov = outv + (ln * 64 + k) * 3;
        ov[0] = coef * v20; ov[1] = coef * v21; ov[2] = coef * v22;
        __syncthreads();

        const float* osr = outs + ln * 64;
        const float* ovr = outv + ln * 192;
        float so = 0.f, vo0 = 0.f, vo1 = 0.f, vo2 = 0.f;
        #pragma unroll 8
        for (int kk = 0; kk < 64; kk++) {
            float p0 = wp0s[kk * 64 + k];
            float p1 = wp1s[kk * 64 + k];
            so  += osr[kk] * p0;
            vo0 += ovr[kk * 3 + 0] * p1;
            vo1 += ovr[kk * 3 + 1] * p1;
            vo2 += ovr[kk * 3 + 2] * p1;
        }
        float* op = out + (size_t)node * 256;
        op[k] = so * INV_SQRT_C;
        op[64 + k * 3 + 0] = vo0 * INV_SQRT_C;
        op[64 + k * 3 + 1] = vo1 * INV_SQRT_C;
        op[64 + k * 3 + 2] = vo2 * INV_SQRT_C;
    }
}

// ================= host =================
static double host_c_silu_m2() {
    const int N = 100000;
    const double a = -13.0, b = 13.0;
    const double h = (b - a) / N;
    double sum = 0.0;
    for (int i = 0; i <= N; i++) {
        double z = a + h * i;
        double f = z / (1.0 + exp(-z));
        double w = exp(-0.5 * z * z);
        double coef = (i == 0 || i == N) ? 1.0 : ((i & 1) ? 4.0 : 2.0);
        sum += coef * f * f * w;
    }
    sum *= h / 3.0;
    sum /= sqrt(2.0 * 3.14159265358979323846);
    return sum;
}

extern "C" void kernel_launch(void* const* d_in, const int* in_sizes, int n_in,
                              void* d_out, int out_size)
{
    const float* node_feats     = (const float*)d_in[0];
    const float* edge_feats     = (const float*)d_in[1];
    const float* edge_attrs     = (const float*)d_in[2];
    const int*   iedges         = (const int*)d_in[3];
    const int*   jedges         = (const int*)d_in[4];
    const int*   atomic_numbers = (const int*)d_in[5];
    const float* Wup0 = (const float*)d_in[6];
    const float* Wup1 = (const float*)d_in[7];
    const float* Wm1  = (const float*)d_in[8];
    const float* Wm2  = (const float*)d_in[9];
    const float* Wm3  = (const float*)d_in[10];
    const float* Wm4  = (const float*)d_in[11];
    const float* Wl0  = (const float*)d_in[12];
    const float* Wl1  = (const float*)d_in[13];
    const float* Ws0c1 = (const float*)d_in[14];
    const float* Ws0c2 = (const float*)d_in[15];
    const float* Ws0c3 = (const float*)d_in[16];
    const float* Ws1c1 = (const float*)d_in[17];
    const float* Ws1c2 = (const float*)d_in[18];
    const float* Ws1c3 = (const float*)d_in[19];
    const float* Wp0  = (const float*)d_in[20];
    const float* Wp1  = (const float*)d_in[21];

    int dev = 0;
    cudaGetDevice(&dev);
    int nsm = 148;
    cudaDeviceGetAttribute(&nsm, cudaDevAttrMultiProcessorCount, dev);

    const int smem_k2  = 215040;   // 29184 floats + 12*1024 u64
    const int smem_k3b = 33280 * 4;
    cudaFuncSetAttribute(k2_mlp,       cudaFuncAttributeMaxDynamicSharedMemorySize, smem_k2);
    cudaFuncSetAttribute(k3b_node_out, cudaFuncAttributeMaxDynamicSharedMemorySize, smem_k3b);

    float c_silu = (float)(1.0 / sqrt(host_c_silu_m2()));

    kc_zero<<<(NN + 255) / 256, 256>>>();
    k_node_up<<<nsm * 4, 256>>>(node_feats, Wup0, Wup1, jedges);   // + histogram
    kc_scan<<<1, 1024>>>();
    kc_fill<<<(NEDGE + 255) / 256, 256>>>(jedges, iedges, edge_attrs);

    k2_mlp<<<nsm, 384, smem_k2>>>(edge_feats, Wm1, Wm2, Wm3, Wm4, c_silu);
    k3a_gather<<<(NN + 3) / 4, 256>>>();
    k3b_node_out<<<nsm, 256, smem_k3b>>>(Wl0, Wl1, atomic_numbers,
                                         Ws0c1, Ws0c2, Ws0c3, Ws1c1, Ws1c2, Ws1c3,
                                         Wp0, Wp1, (float*)d_out);
}

// round 5
// speedup vs baseline: 1.0889x; 1.0889x over previous
#include <cuda_runtime.h>
#include <math.h>

#define NN     20000
#define NEDGE  320000

typedef unsigned long long u64;

// ---------------- device scratch ----------------
__device__ float4 g_xsv[NN * 64];                 // (xv0,xv1,xv2,xs) per node-channel
__device__ float  g_tpw[(size_t)NEDGE * 320];     // edge MLP output, edge-ordered
__device__ float  g_msg_s[NN * 128];
__device__ float  g_msg_v[NN * 768];              // [node][ch(192)][4] padded
__device__ int    g_cnt[NN];
__device__ int    g_off[NN + 1];
__device__ int    g_fill[NN];
__device__ int    g_eidx[NEDGE];                  // CSR slot -> edge
__device__ int    g_ni_r[NEDGE];                  // CSR-ordered iedges
__device__ float4 g_ea_r[NEDGE];                  // CSR-ordered edge_attrs

// ---------------- constants ----------------
#define INV_SQRT_C    0.125f
#define INV_SQRT_NB   0.3535533905932738f
#define INV_SQRT_64   0.125f
#define INV_SQRT_2C   0.08838834764831845f
#define INV_SQRT_3C   0.07216878364870323f
#define INV_SQRT3     0.5773502691896258f
#define INV_SQRT2     0.7071067811865476f

// ---------------- f32x2 helpers ----------------
__device__ __forceinline__ u64 ffma2(u64 a, u64 b, u64 c) {
    u64 d;
    asm("fma.rn.f32x2 %0, %1, %2, %3;" : "=l"(d) : "l"(a), "l"(b), "l"(c));
    return d;
}
__device__ __forceinline__ u64 dup2(float x) {
    u64 d; unsigned r = __float_as_uint(x);
    asm("mov.b64 %0, {%1, %1};" : "=l"(d) : "r"(r));
    return d;
}
__device__ __forceinline__ u64 pk2(float lo, float hi) {
    u64 d;
    asm("mov.b64 %0, {%1, %2};" : "=l"(d) : "r"(__float_as_uint(lo)), "r"(__float_as_uint(hi)));
    return d;
}
__device__ __forceinline__ float2 unpk(u64 v) {
    unsigned lo, hi;
    asm("mov.b64 {%0, %1}, %2;" : "=r"(lo), "=r"(hi) : "l"(v));
    return make_float2(__uint_as_float(lo), __uint_as_float(hi));
}
__device__ __forceinline__ u64 silu2(u64 v, float cs) {
    float2 f = unpk(v);
    f.x = cs * f.x / (1.f + __expf(-f.x));
    f.y = cs * f.y / (1.f + __expf(-f.y));
    return pk2(f.x, f.y);
}

// ================= CSR =================
__global__ void kc_zero() {
    int i = blockIdx.x * 256 + threadIdx.x;
    if (i < NN) g_cnt[i] = 0;
}
__global__ void __launch_bounds__(1024) kc_scan() {
    __shared__ int part[1024];
    int tid = threadIdx.x;
    int base = tid * 20;
    int loc[20];
    int s = 0;
    #pragma unroll
    for (int i = 0; i < 20; i++) {
        int g = base + i;
        int v = (g < NN) ? g_cnt[g] : 0;
        loc[i] = s; s += v;
    }
    part[tid] = s;
    __syncthreads();
    for (int off = 1; off < 1024; off <<= 1) {
        int v = (tid >= off) ? part[tid - off] : 0;
        __syncthreads();
        part[tid] += v;
        __syncthreads();
    }
    int pre = (tid == 0) ? 0 : part[tid - 1];
    #pragma unroll
    for (int i = 0; i < 20; i++) {
        int g = base + i;
        if (g < NN) { int o = pre + loc[i]; g_off[g] = o; g_fill[g] = o; }
    }
    if (tid == 0) g_off[NN] = NEDGE;
}
__global__ void kc_fill(const int* __restrict__ jedges,
                        const int* __restrict__ iedges,
                        const float* __restrict__ edge_attrs) {
    int e = blockIdx.x * 256 + threadIdx.x;
    if (e < NEDGE) {
        int pos = atomicAdd(&g_fill[jedges[e]], 1);
        g_eidx[pos] = e;
        g_ni_r[pos] = iedges[e];
        g_ea_r[pos] = ((const float4*)edge_attrs)[e];
    }
}

// ================= Kernel 1: node up-projection (+ fused jedges histogram) ==
__global__ void __launch_bounds__(256) k_node_up(
    const float* __restrict__ node_feats,
    const float* __restrict__ Wup0,
    const float* __restrict__ Wup1,
    const int*   __restrict__ jedges)
{
    __shared__ float w0s[4096];
    __shared__ float w1s[4096];
    __shared__ float fs[4 * 256];
    int tid = threadIdx.x;
    for (int i = tid; i < 4096; i += 256) { w0s[i] = Wup0[i]; w1s[i] = Wup1[i]; }

    int gtid = blockIdx.x * 256 + tid;
    int gstr = gridDim.x * 256;
    for (int e = gtid; e < NEDGE; e += gstr) atomicAdd(&g_cnt[jedges[e]], 1);

    int ln = tid >> 6;
    int k  = tid & 63;
    for (int base = blockIdx.x * 4; base < NN; base += gridDim.x * 4) {
        __syncthreads();
        for (int i = tid; i < 1024; i += 256) fs[i] = node_feats[base * 256 + i];
        __syncthreads();
        const float* f = fs + ln * 256;
        float accs = 0.f, av0 = 0.f, av1 = 0.f, av2 = 0.f;
        #pragma unroll 8
        for (int c = 0; c < 64; c++) {
            float w0 = w0s[c * 64 + k];
            float w1 = w1s[c * 64 + k];
            accs += f[c] * w0;
            av0  += f[64 + 3 * c + 0] * w1;
            av1  += f[64 + 3 * c + 1] * w1;
            av2  += f[64 + 3 * c + 2] * w1;
        }
        int node = base + ln;
        g_xsv[node * 64 + k] = make_float4(av0 * INV_SQRT_C, av1 * INV_SQRT_C,
                                           av2 * INV_SQRT_C, accs * INV_SQRT_C);
    }
}

// ================= Kernel 2: edge MLP, edge-pair f32x2 packing ==============
// 12 warps/block, 16 edges (8 pairs) per warp-iteration. Activations live in
// per-warp SMEM as (edge_even, edge_odd) f32x2 words: buf[pair*64 + j].
// One FFMA2 computes one output channel for two edges. Weights: LDS.32 +
// in-register dup (amortized over 8-16 FFMA2). Activation reads are broadcast
// LDS.128 (two j per load). Layer outputs are produced directly in packed
// format -> no repacking between layers.

template<int K>
__device__ __forceinline__ void mlp_layer(
    const float* __restrict__ W, const u64* __restrict__ src, u64* __restrict__ dst,
    int lane, float cs)
{
    u64 aL[8], aH[8];
    #pragma unroll
    for (int p = 0; p < 8; p++) { aL[p] = 0ull; aH[p] = 0ull; }
    #pragma unroll 4
    for (int jj = 0; jj < K / 2; jj++) {
        ulonglong2 h[8];
        #pragma unroll
        for (int p = 0; p < 8; p++)
            h[p] = *(const ulonglong2*)(src + p * 64 + 2 * jj);
        #pragma unroll
        for (int s = 0; s < 2; s++) {
            int j = 2 * jj + s;
            u64 wl = dup2(W[j * 64 + lane]);
            u64 wh = dup2(W[j * 64 + lane + 32]);
            #pragma unroll
            for (int p = 0; p < 8; p++) {
                u64 hp = s ? h[p].y : h[p].x;
                aL[p] = ffma2(hp, wl, aL[p]);
                aH[p] = ffma2(hp, wh, aH[p]);
            }
        }
    }
    __syncwarp();
    #pragma unroll
    for (int p = 0; p < 8; p++) {
        dst[p * 64 + lane]      = silu2(aL[p], cs);
        dst[p * 64 + lane + 32] = silu2(aH[p], cs);
    }
    __syncwarp();
}

__global__ void __launch_bounds__(384, 1) k2_mlp(
    const float* __restrict__ edge_feats,
    const float* __restrict__ Wm1,
    const float* __restrict__ Wm2,
    const float* __restrict__ Wm3,
    const float* __restrict__ Wm4,
    float c_silu)
{
    extern __shared__ float sm[];
    float* w1s = sm;                 // 512
    float* w2s = sm + 512;           // 4096
    float* w3s = sm + 4608;          // 4096
    float* w4s = sm + 8704;          // 20480
    u64* hb = (u64*)(sm + 29184);    // 12 warps * 1024 u64 (two 512-u64 bufs)

    int tid = threadIdx.x;
    for (int i = tid; i < 512;   i += 384) w1s[i] = Wm1[i] * INV_SQRT_NB;
    for (int i = tid; i < 4096;  i += 384) { w2s[i] = Wm2[i] * INV_SQRT_64; w3s[i] = Wm3[i] * INV_SQRT_64; }
    for (int i = tid; i < 20480; i += 384) w4s[i] = Wm4[i] * INV_SQRT_64;
    __syncthreads();

    int warp = tid >> 5, lane = tid & 31;
    u64* bufA = hb + warp * 1024;
    u64* bufB = bufA + 512;

    for (int e0 = (blockIdx.x * 12 + warp) * 16; e0 < NEDGE; e0 += gridDim.x * 12 * 16) {
        // ---- pack inputs: bufA[p*64+i] = (ef[e0+2p][i], ef[e0+2p+1][i]) ----
        #pragma unroll
        for (int r = 0; r < 2; r++) {
            int idx = lane + r * 32;       // 0..63
            int p = idx >> 3, i = idx & 7;
            float a = edge_feats[(e0 + 2 * p) * 8 + i];
            float b = edge_feats[(e0 + 2 * p + 1) * 8 + i];
            bufA[p * 64 + i] = pk2(a, b);
        }
        __syncwarp();

        mlp_layer<8> (w1s, bufA, bufB, lane, c_silu);   // layer 1: 8 -> 64
        mlp_layer<64>(w2s, bufB, bufA, lane, c_silu);   // layer 2: 64 -> 64
        mlp_layer<64>(w3s, bufA, bufB, lane, c_silu);   // layer 3: 64 -> 64

        // ---- layer 4: 64 -> 320, two 4-pair halves (register pressure) ----
        #pragma unroll
        for (int half = 0; half < 2; half++) {
            u64 aL[4][5], aH[4][5];
            #pragma unroll
            for (int q = 0; q < 4; q++)
                #pragma unroll
                for (int b = 0; b < 5; b++) { aL[q][b] = 0ull; aH[q][b] = 0ull; }

            #pragma unroll 2
            for (int jj = 0; jj < 32; jj++) {
                ulonglong2 h[4];
                #pragma unroll
                for (int q = 0; q < 4; q++)
                    h[q] = *(const ulonglong2*)(bufB + (half * 4 + q) * 64 + 2 * jj);
                #pragma unroll
                for (int s = 0; s < 2; s++) {
                    int j = 2 * jj + s;
                    #pragma unroll
                    for (int b = 0; b < 5; b++) {
                        u64 wl = dup2(w4s[j * 320 + b * 64 + lane]);
                        u64 wh = dup2(w4s[j * 320 + b * 64 + lane + 32]);
                        #pragma unroll
                        for (int q = 0; q < 4; q++) {
                            u64 hp = s ? h[q].y : h[q].x;
                            aL[q][b] = ffma2(hp, wl, aL[q][b]);
                            aH[q][b] = ffma2(hp, wh, aH[q][b]);
                        }
                    }
                }
            }
            #pragma unroll
            for (int q = 0; q < 4; q++) {
                int p = half * 4 + q;
                float* d0 = g_tpw + (size_t)(e0 + 2 * p) * 320;
                float* d1 = d0 + 320;
                #pragma unroll
                for (int b = 0; b < 5; b++) {
                    float2 lo = unpk(aL[q][b]);
                    float2 hi = unpk(aH[q][b]);
                    d0[b * 64 + lane]      = lo.x;
                    d1[b * 64 + lane]      = lo.y;
                    d0[b * 64 + lane + 32] = hi.x;
                    d1[b * 64 + lane + 32] = hi.y;
                }
            }
        }
        __syncwarp();
    }
}

// ================= Kernel 3a: CSR gather — messages, no atomics =============
__global__ void __launch_bounds__(256) k3a_gather()
{
    int tid = threadIdx.x;
    int nl = tid >> 6;
    int c  = tid & 63;
    int node = blockIdx.x * 4 + nl;
    if (node >= NN) return;
    int beg = g_off[node], end = g_off[node + 1];

    float ms0 = 0.f, ms1 = 0.f;
    float m20 = 0.f, m21 = 0.f, m22 = 0.f;
    float m30 = 0.f, m31 = 0.f, m32 = 0.f;
    float m40 = 0.f, m41 = 0.f, m42 = 0.f;

    #pragma unroll 2
    for (int p = beg; p < end; p++) {
        int e  = g_eidx[p];
        int ni = g_ni_r[p];
        float4 ea = g_ea_r[p];                        // (eas, ev0, ev1, ev2)
        const float* tw = g_tpw + (size_t)e * 320;
        float wa = tw[c], wb = tw[64 + c], wc = tw[128 + c], wd = tw[192 + c], we = tw[256 + c];
        float4 x = g_xsv[(size_t)ni * 64 + c];        // (xv0, xv1, xv2, xs)

        ms0 += wa * x.w * ea.x;
        ms1 += wb * (x.x * ea.y + x.y * ea.z + x.z * ea.w) * INV_SQRT3;
        float t2 = wc * x.w;
        m20 += t2 * ea.y; m21 += t2 * ea.z; m22 += t2 * ea.w;
        float t3 = wd * ea.x;
        m30 += t3 * x.x;  m31 += t3 * x.y;  m32 += t3 * x.z;
        float wei = we * INV_SQRT2;
        m40 += wei * (x.y * ea.w - x.z * ea.z);
        m41 += wei * (x.z * ea.y - x.x * ea.w);
        m42 += wei * (x.x * ea.z - x.y * ea.y);
    }

    g_msg_s[node * 128 + c]      = ms0;
    g_msg_s[node * 128 + 64 + c] = ms1;
    float4* mv = (float4*)(g_msg_v + (size_t)node * 768);
    mv[c]       = make_float4(m20, m21, m22, 0.f);
    mv[64 + c]  = make_float4(m30, m31, m32, 0.f);
    mv[128 + c] = make_float4(m40, m41, m42, 0.f);
}

// ================= Kernel 3b: node linear + polynomial mixing + output ======
__global__ void __launch_bounds__(256) k3b_node_out(
    const float* __restrict__ Wl0, const float* __restrict__ Wl1,
    const int*   __restrict__ atomic_numbers,
    const float* __restrict__ Ws0c1, const float* __restrict__ Ws0c2, const float* __restrict__ Ws0c3,
    const float* __restrict__ Ws1c1, const float* __restrict__ Ws1c2, const float* __restrict__ Ws1c3,
    const float* __restrict__ Wp0,   const float* __restrict__ Wp1,
    float* __restrict__ out)
{
    extern __shared__ float sm[];
    float* wl0s = sm;              // 8192
    float* wl1s = wl0s + 8192;     // 12288
    float* wp0s = wl1s + 12288;    // 4096
    float* wp1s = wp0s + 4096;     // 4096
    float* msgs = wp1s + 4096;     // 512
    float* msgv = msgs + 512;      // 3072
    float* outs = msgv + 3072;     // 256
    float* outv = outs + 256;      // 768   total 33280 floats

    int tid = threadIdx.x;
    for (int i = tid; i < 8192;  i += 256) wl0s[i] = Wl0[i];
    for (int i = tid; i < 12288; i += 256) wl1s[i] = Wl1[i];
    for (int i = tid; i < 4096;  i += 256) { wp0s[i] = Wp0[i]; wp1s[i] = Wp1[i]; }

    int ln = tid >> 6;
    int k  = tid & 63;
    for (int base = blockIdx.x * 4; base < NN; base += gridDim.x * 4) {
        __syncthreads();
        for (int i = tid; i < 512;  i += 256) msgs[i] = g_msg_s[(size_t)base * 128 + i];
        for (int i = tid; i < 3072; i += 256) msgv[i] = g_msg_v[(size_t)base * 768 + i];
        __syncthreads();

        int node = base + ln;
        const float* ms = msgs + ln * 128;
        const float* mv = msgv + ln * 768;

        float s2 = 0.f;
        #pragma unroll 8
        for (int c = 0; c < 128; c++) s2 += ms[c] * wl0s[c * 64 + k];
        s2 *= INV_SQRT_2C;

        float v20 = 0.f, v21 = 0.f, v22 = 0.f;
        #pragma unroll 4
        for (int c = 0; c < 192; c++) {
            float w = wl1s[c * 64 + k];
            v20 += mv[c * 4 + 0] * w;
            v21 += mv[c * 4 + 1] * w;
            v22 += mv[c * 4 + 2] * w;
        }
        v20 *= INV_SQRT_3C; v21 *= INV_SQRT_3C; v22 *= INV_SQRT_3C;

        float vv = v20 * v20 + v21 * v21 + v22 * v22;
        int z = atomic_numbers[node];
        float w01  = Ws0c1[z * 64 + k];
        float w02a = Ws0c2[z * 128 + k];
        float w02b = Ws0c2[z * 128 + 64 + k];
        float w03a = Ws0c3[z * 128 + k];
        float w03b = Ws0c3[z * 128 + 64 + k];
        float w11  = Ws1c1[z * 64 + k];
        float w12  = Ws1c2[z * 64 + k];
        float w13a = Ws1c3[z * 128 + k];
        float w13b = Ws1c3[z * 128 + 64 + k];

        float vvs = vv * INV_SQRT3;
        float s2s = s2 * s2;
        float os   = w01 * s2 + w02a * s2s + w02b * vvs + w03a * s2s * s2 + w03b * s2 * vvs;
        float coef = w11 + w12 * s2 + w13a * s2s + w13b * vvs;

        outs[ln * 64 + k] = os;
        float* ov = outv + (ln * 64 + k) * 3;
        ov[0] = coef * v20; ov[1] = coef * v21; ov[2] = coef * v22;
        __syncthreads();

        const float* osr = outs + ln * 64;
        const float* ovr = outv + ln * 192;
        float so = 0.f, vo0 = 0.f, vo1 = 0.f, vo2 = 0.f;
        #pragma unroll 8
        for (int kk = 0; kk < 64; kk++) {
            float p0 = wp0s[kk * 64 + k];
            float p1 = wp1s[kk * 64 + k];
            so  += osr[kk] * p0;
            vo0 += ovr[kk * 3 + 0] * p1;
            vo1 += ovr[kk * 3 + 1] * p1;
            vo2 += ovr[kk * 3 + 2] * p1;
        }
        float* op = out + (size_t)node * 256;
        op[k] = so * INV_SQRT_C;
        op[64 + k * 3 + 0] = vo0 * INV_SQRT_C;
        op[64 + k * 3 + 1] = vo1 * INV_SQRT_C;
        op[64 + k * 3 + 2] = vo2 * INV_SQRT_C;
    }
}

// ================= host =================
static double host_c_silu_m2() {
    const int N = 100000;
    const double a = -13.0, b = 13.0;
    const double h = (b - a) / N;
    double sum = 0.0;
    for (int i = 0; i <= N; i++) {
        double z = a + h * i;
        double f = z / (1.0 + exp(-z));
        double w = exp(-0.5 * z * z);
        double coef = (i == 0 || i == N) ? 1.0 : ((i & 1) ? 4.0 : 2.0);
        sum += coef * f * f * w;
    }
    sum *= h / 3.0;
    sum /= sqrt(2.0 * 3.14159265358979323846);
    return sum;
}

extern "C" void kernel_launch(void* const* d_in, const int* in_sizes, int n_in,
                              void* d_out, int out_size)
{
    const float* node_feats     = (const float*)d_in[0];
    const float* edge_feats     = (const float*)d_in[1];
    const float* edge_attrs     = (const float*)d_in[2];
    const int*   iedges         = (const int*)d_in[3];
    const int*   jedges         = (const int*)d_in[4];
    const int*   atomic_numbers = (const int*)d_in[5];
    const float* Wup0 = (const float*)d_in[6];
    const float* Wup1 = (const float*)d_in[7];
    const float* Wm1  = (const float*)d_in[8];
    const float* Wm2  = (const float*)d_in[9];
    const float* Wm3  = (const float*)d_in[10];
    const float* Wm4  = (const float*)d_in[11];
    const float* Wl0  = (const float*)d_in[12];
    const float* Wl1  = (const float*)d_in[13];
    const float* Ws0c1 = (const float*)d_in[14];
    const float* Ws0c2 = (const float*)d_in[15];
    const float* Ws0c3 = (const float*)d_in[16];
    const float* Ws1c1 = (const float*)d_in[17];
    const float* Ws1c2 = (const float*)d_in[18];
    const float* Ws1c3 = (const float*)d_in[19];
    const float* Wp0  = (const float*)d_in[20];
    const float* Wp1  = (const float*)d_in[21];

    int dev = 0;
    cudaGetDevice(&dev);
    int nsm = 148;
    cudaDeviceGetAttribute(&nsm, cudaDevAttrMultiProcessorCount, dev);

    const int smem_k2  = 29184 * 4 + 12 * 1024 * 8;   // 215040 B
    const int smem_k3b = 33280 * 4;
    cudaFuncSetAttribute(k2_mlp,       cudaFuncAttributeMaxDynamicSharedMemorySize, smem_k2);
    cudaFuncSetAttribute(k3b_node_out, cudaFuncAttributeMaxDynamicSharedMemorySize, smem_k3b);

    float c_silu = (float)(1.0 / sqrt(host_c_silu_m2()));

    kc_zero<<<(NN + 255) / 256, 256>>>();
    k_node_up<<<nsm * 4, 256>>>(node_feats, Wup0, Wup1, jedges);   // + histogram
    kc_scan<<<1, 1024>>>();
    kc_fill<<<(NEDGE + 255) / 256, 256>>>(jedges, iedges, edge_attrs);

    k2_mlp<<<nsm, 384, smem_k2>>>(edge_feats, Wm1, Wm2, Wm3, Wm4, c_silu);
    k3a_gather<<<(NN + 3) / 4, 256>>>();
    k3b_node_out<<<nsm, 256, smem_k3b>>>(Wl0, Wl1, atomic_numbers,
                                         Ws0c1, Ws0c2, Ws0c3, Ws1c1, Ws1c2, Ws1c3,
                                         Wp0, Wp1, (float*)d_out);
}